// round 12
// baseline (speedup 1.0000x reference)
#include <cuda_runtime.h>
#include <cuda_bf16.h>

// Problem constants
#define N_ROWS 16384
#define SPLIT  100
#define IDIM   128
#define NH     4
#define PD     64
#define OUTD   (NH * PD)        // 256
#define MITERS (SPLIT / 2)      // 50 iters, 1KB (2 segments) each
#define NWARP  4                // warps (rows) per block

// wq[h][i] = sum_o W[h,i,o] * q[h,o]  — precomputed by a tiny kernel
__device__ float g_wq[NH * IDIM];

__global__ void wq_kernel(const float* __restrict__ W, const float* __restrict__ q) {
    int idx = threadIdx.x;                     // 512 threads
    if (idx >= NH * IDIM) return;
    int h = idx >> 7, i = idx & 127;
    const float* Wr = W + ((size_t)(h * IDIM + i)) * PD;
    const float* qr = q + h * PD;
    float acc = 0.f;
#pragma unroll
    for (int o = 0; o < PD; o++) acc = fmaf(Wr[o], qr[o], acc);
    g_wq[idx] = acc;
}

__global__ void __launch_bounds__(NWARP * 32, 7)
attn_kernel(const float* __restrict__ x, const float* __restrict__ W,
            float* __restrict__ out) {
    // epilogue staging only (no mainloop smem at all)
    __shared__ float sx[NWARP * 512];            // 8 KB: row r at sx[r*512 + h*128 + i]
    __shared__ float sdsum[NWARP][NH];           // per-row softmax denominators

    const int warp = threadIdx.x >> 5;
    const int lane = threadIdx.x & 31;
    const int half = lane >> 4;                 // head-pair owner: heads {2*half, 2*half+1}
    const int p16  = lane & 15;                 // owns i in [p16*8, p16*8+8) of BOTH segments
    const int b3   = (p16 >> 3) & 1;            // head selector within the pair
    const int b2   = (p16 >> 2) & 1;            // segment selector (A/B)
    const int row  = blockIdx.x * NWARP + warp; // grid sized exactly: always < N_ROWS
    // lane's base: i-slice of segment A of chunk 0; seg B is +128 floats (+32 float4)
    const float4* xp = (const float4*)(x + (size_t)row * (SPLIT * IDIM)) + p16 * 2;

    // wq fragment: this lane's 8 i-values for its 2 heads (16 regs)
    float4 wqa0, wqa1, wqb0, wqb1;
    {
        const float4* ga = (const float4*)(g_wq + (2 * half) * IDIM + p16 * 8);
        const float4* gb = (const float4*)(g_wq + (2 * half + 1) * IDIM + p16 * 8);
        wqa0 = ga[0]; wqa1 = ga[1];
        wqb0 = gb[0]; wqb1 = gb[1];
    }

    // accumulators: 2 heads x 8 i (16 regs) + 2 denominators
    float4 xh0a, xh0b, xh1a, xh1b;
    xh0a = xh0b = xh1a = xh1b = make_float4(0.f, 0.f, 0.f, 0.f);
    float ds0 = 0.f, ds1 = 0.f;

    // register double-buffer: prefetch iteration 0 (seg A: +0,+1; seg B: +32,+33)
    float4 A0 = xp[0], A1 = xp[1], B0 = xp[32], B1 = xp[33];

    for (int t = 0; t < MITERS; t++) {
        float4 xa0 = A0, xa1 = A1, xb0v = B0, xb1v = B1;

        // prefetch next 1KB chunk (stride 64 float4) into the other buffer half
        if (t + 1 < MITERS) {
            const float4* p = xp + (t + 1) * 64;
            A0 = p[0]; A1 = p[1]; B0 = p[32]; B1 = p[33];
        }

        // partial scores: 2 heads x 2 segments over this lane's 8 i's
        float pA0, pA1, pB0, pB1;
        {
            float a;
            a = xa0.x * wqa0.x;  a = fmaf(xa0.y, wqa0.y, a); a = fmaf(xa0.z, wqa0.z, a); a = fmaf(xa0.w, wqa0.w, a);
            a = fmaf(xa1.x, wqa1.x, a); a = fmaf(xa1.y, wqa1.y, a); a = fmaf(xa1.z, wqa1.z, a); a = fmaf(xa1.w, wqa1.w, a);
            pA0 = a;
            a = xa0.x * wqb0.x;  a = fmaf(xa0.y, wqb0.y, a); a = fmaf(xa0.z, wqb0.z, a); a = fmaf(xa0.w, wqb0.w, a);
            a = fmaf(xa1.x, wqb1.x, a); a = fmaf(xa1.y, wqb1.y, a); a = fmaf(xa1.z, wqb1.z, a); a = fmaf(xa1.w, wqb1.w, a);
            pA1 = a;
            a = xb0v.x * wqa0.x; a = fmaf(xb0v.y, wqa0.y, a); a = fmaf(xb0v.z, wqa0.z, a); a = fmaf(xb0v.w, wqa0.w, a);
            a = fmaf(xb1v.x, wqa1.x, a); a = fmaf(xb1v.y, wqa1.y, a); a = fmaf(xb1v.z, wqa1.z, a); a = fmaf(xb1v.w, wqa1.w, a);
            pB0 = a;
            a = xb0v.x * wqb0.x; a = fmaf(xb0v.y, wqb0.y, a); a = fmaf(xb0v.z, wqb0.z, a); a = fmaf(xb0v.w, wqb0.w, a);
            a = fmaf(xb1v.x, wqb1.x, a); a = fmaf(xb1v.y, wqb1.y, a); a = fmaf(xb1v.z, wqb1.z, a); a = fmaf(xb1v.w, wqb1.w, a);
            pB1 = a;
        }

        // specialized butterfly within the 16-lane half: outputs (2 heads x 2 segs)
        float s1 = b3 ? pA0 : pA1;
        float r1 = __shfl_xor_sync(0xffffffffu, s1, 8);
        float uA = (b3 ? pA1 : pA0) + r1;
        float s2 = b3 ? pB0 : pB1;
        float r2 = __shfl_xor_sync(0xffffffffu, s2, 8);
        float uB = (b3 ? pB1 : pB0) + r2;
        float s3 = b2 ? uA : uB;
        float r3 = __shfl_xor_sync(0xffffffffu, s3, 4);
        float v  = (b2 ? uB : uA) + r3;              // (head 2*half+b3, seg b2)
        v += __shfl_xor_sync(0xffffffffu, v, 2);
        v += __shfl_xor_sync(0xffffffffu, v, 1);

        // leaky_relu -> exp, ONE per lane (|score| <~ 15 << 88, fp32-safe)
        float e = __expf(fmaxf(v, 0.2f * v));

        // allgather within the half (3 shfls): lane needs its 2 heads x 2 segs
        float g1 = __shfl_xor_sync(0xffffffffu, e, 4);
        float eX = b2 ? g1 : e;     // (head 2*half+b3, seg A)
        float eY = b2 ? e  : g1;    // (head 2*half+b3, seg B)
        float g2 = __shfl_xor_sync(0xffffffffu, eX, 8);
        float g3 = __shfl_xor_sync(0xffffffffu, eY, 8);
        float eA0 = b3 ? g2 : eX;   // (head 2*half,   seg A)
        float eA1 = b3 ? eX : g2;   // (head 2*half+1, seg A)
        float eB0 = b3 ? g3 : eY;   // (head 2*half,   seg B)
        float eB1 = b3 ? eY : g3;   // (head 2*half+1, seg B)

        // accumulate: 2 heads x 8 i x 2 segments
        ds0 += eA0 + eB0;
        ds1 += eA1 + eB1;
        xh0a.x = fmaf(eA0, xa0.x, xh0a.x); xh0a.y = fmaf(eA0, xa0.y, xh0a.y);
        xh0a.z = fmaf(eA0, xa0.z, xh0a.z); xh0a.w = fmaf(eA0, xa0.w, xh0a.w);
        xh0b.x = fmaf(eA0, xa1.x, xh0b.x); xh0b.y = fmaf(eA0, xa1.y, xh0b.y);
        xh0b.z = fmaf(eA0, xa1.z, xh0b.z); xh0b.w = fmaf(eA0, xa1.w, xh0b.w);
        xh1a.x = fmaf(eA1, xa0.x, xh1a.x); xh1a.y = fmaf(eA1, xa0.y, xh1a.y);
        xh1a.z = fmaf(eA1, xa0.z, xh1a.z); xh1a.w = fmaf(eA1, xa0.w, xh1a.w);
        xh1b.x = fmaf(eA1, xa1.x, xh1b.x); xh1b.y = fmaf(eA1, xa1.y, xh1b.y);
        xh1b.z = fmaf(eA1, xa1.z, xh1b.z); xh1b.w = fmaf(eA1, xa1.w, xh1b.w);

        xh0a.x = fmaf(eB0, xb0v.x, xh0a.x); xh0a.y = fmaf(eB0, xb0v.y, xh0a.y);
        xh0a.z = fmaf(eB0, xb0v.z, xh0a.z); xh0a.w = fmaf(eB0, xb0v.w, xh0a.w);
        xh0b.x = fmaf(eB0, xb1v.x, xh0b.x); xh0b.y = fmaf(eB0, xb1v.y, xh0b.y);
        xh0b.z = fmaf(eB0, xb1v.z, xh0b.z); xh0b.w = fmaf(eB0, xb1v.w, xh0b.w);
        xh1a.x = fmaf(eB1, xb0v.x, xh1a.x); xh1a.y = fmaf(eB1, xb0v.y, xh1a.y);
        xh1a.z = fmaf(eB1, xb0v.z, xh1a.z); xh1a.w = fmaf(eB1, xb0v.w, xh1a.w);
        xh1b.x = fmaf(eB1, xb1v.x, xh1b.x); xh1b.y = fmaf(eB1, xb1v.y, xh1b.y);
        xh1b.z = fmaf(eB1, xb1v.z, xh1b.z); xh1b.w = fmaf(eB1, xb1v.w, xh1b.w);
    }

    // ---- stage UNNORMALIZED accumulators for ALL rows (dedicated smem) ----
    // Halves own disjoint heads, lanes own disjoint i — no combine needed.
    {
        float4* d0 = (float4*)(sx + warp * 512 + (2 * half) * IDIM + p16 * 8);
        d0[0] = xh0a;
        d0[1] = xh0b;
        float4* d1 = (float4*)(sx + warp * 512 + (2 * half + 1) * IDIM + p16 * 8);
        d1[0] = xh1a;
        d1[1] = xh1b;
    }
    if (p16 == 0) {
        sdsum[warp][2 * half]     = ds0;
        sdsum[warp][2 * half + 1] = ds1;
    }
    __syncthreads();

    // ---- cooperative epilogue: warp w = head w, lane owns 2 output cols,
    //      each W float2 load amortized across all 4 rows (8 FMAs/load) ----
    {
        const int hh = warp;              // head handled by this warp
        const int c0 = lane * 2;          // output columns c0, c0+1
        const float* Wp = W + ((size_t)hh * IDIM) * PD + c0;  // W[hh][i][c0], stride PD per i
        const float* sxh = sx + hh * IDIM;                    // + r*512 per row

        float2 acc[NWARP];
#pragma unroll
        for (int r = 0; r < NWARP; r++) acc[r] = make_float2(0.f, 0.f);

#pragma unroll 4
        for (int i = 0; i < IDIM; i++) {
            float2 wv = *(const float2*)(Wp + i * PD);         // shared by all 4 rows
#pragma unroll
            for (int r = 0; r < NWARP; r++) {
                float xv = sxh[r * 512 + i];                   // LDS broadcast
                acc[r].x = fmaf(xv, wv.x, acc[r].x);
                acc[r].y = fmaf(xv, wv.y, acc[r].y);
            }
        }

#pragma unroll
        for (int r = 0; r < NWARP; r++) {
            float inv = 1.0f / sdsum[r][hh];
            int row_r = blockIdx.x * NWARP + r;
            float2* op = (float2*)(out + (size_t)row_r * OUTD + hh * PD + c0);
            *op = make_float2(acc[r].x * inv, acc[r].y * inv);
        }
    }
}

extern "C" void kernel_launch(void* const* d_in, const int* in_sizes, int n_in,
                              void* d_out, int out_size) {
    // inputs: x [N, 12800], W [4,128,64], q [4,64] — identify defensively by size
    const float* x = (const float*)d_in[0];
    const float* W = (const float*)d_in[1];
    const float* q = (const float*)d_in[2];
    for (int i = 0; i < n_in && i < 3; i++) {
        if (in_sizes[i] == N_ROWS * SPLIT * IDIM) x = (const float*)d_in[i];
        else if (in_sizes[i] == NH * IDIM * PD)   W = (const float*)d_in[i];
        else if (in_sizes[i] == NH * PD)          q = (const float*)d_in[i];
    }
    float* out = (float*)d_out;

    wq_kernel<<<1, 512>>>(W, q);
    attn_kernel<<<N_ROWS / NWARP, NWARP * 32>>>(x, W, out);
}

// round 14
// speedup vs baseline: 1.1178x; 1.1178x over previous
#include <cuda_runtime.h>
#include <cuda_bf16.h>
#include <cstdint>

// Problem constants
#define N_ROWS 16384
#define SPLIT  100
#define IDIM   128
#define NH     4
#define PD     64
#define OUTD   (NH * PD)        // 256
#define MITERS (SPLIT / 2)      // 50 iters, 1KB (2 segments) each
#define SLOTS  4                // ring slots of 1KB each (4KB/warp)
#define PRE    3                // bulk copies in flight per warp
#define NWARP  4                // warps (rows) per block

// wq[h][i] = sum_o W[h,i,o] * q[h,o]  — precomputed by a tiny kernel
__device__ float g_wq[NH * IDIM];

__global__ void wq_kernel(const float* __restrict__ W, const float* __restrict__ q) {
    int idx = threadIdx.x;                     // 512 threads
    if (idx >= NH * IDIM) return;
    int h = idx >> 7, i = idx & 127;
    const float* Wr = W + ((size_t)(h * IDIM + i)) * PD;
    const float* qr = q + h * PD;
    float acc = 0.f;
#pragma unroll
    for (int o = 0; o < PD; o++) acc = fmaf(Wr[o], qr[o], acc);
    g_wq[idx] = acc;
}

__device__ __forceinline__ uint32_t smem_u32(const void* p) {
    return (uint32_t)__cvta_generic_to_shared(p);
}
__device__ __forceinline__ void mbar_init(uint32_t mbar) {
    asm volatile("mbarrier.init.shared.b64 [%0], 1;" :: "r"(mbar) : "memory");
}
__device__ __forceinline__ void mbar_expect_tx_1k(uint32_t mbar) {
    asm volatile("mbarrier.arrive.expect_tx.shared.b64 _, [%0], 1024;" :: "r"(mbar) : "memory");
}
__device__ __forceinline__ void bulk_1kb(uint32_t smem_dst, const void* gsrc, uint32_t mbar) {
    asm volatile(
        "cp.async.bulk.shared::cta.global.mbarrier::complete_tx::bytes [%0], [%1], 1024, [%2];"
        :: "r"(smem_dst), "l"(gsrc), "r"(mbar) : "memory");
}
__device__ __forceinline__ void mbar_wait(uint32_t mbar, uint32_t parity) {
    uint32_t done;
    asm volatile(
        "{\n\t.reg .pred p;\n\t"
        "mbarrier.try_wait.parity.acquire.cta.shared::cta.b64 p, [%1], %2;\n\t"
        "selp.b32 %0, 1, 0, p;\n\t}"
        : "=r"(done) : "r"(mbar), "r"(parity) : "memory");
    if (!done) {
        asm volatile(
            "{\n\t.reg .pred P1;\n\t"
            "WAIT_LOOP_%=:\n\t"
            "mbarrier.try_wait.parity.acquire.cta.shared::cta.b64 P1, [%0], %1, 0x989680;\n\t"
            "@P1 bra.uni WAIT_DONE_%=;\n\t"
            "bra.uni WAIT_LOOP_%=;\n\t"
            "WAIT_DONE_%=:\n\t}"
            :: "r"(mbar), "r"(parity) : "memory");
    }
}

__global__ void __launch_bounds__(NWARP * 32, 8)
attn_kernel(const float* __restrict__ x, const float* __restrict__ W,
            float* __restrict__ out) {
    // per-warp ring: SLOTS slots of 1KB (2 segments, 64 float4)
    __shared__ float4 ring[NWARP][SLOTS][64];                // 16 KB
    __shared__ __align__(8) unsigned long long mbar_s[NWARP][SLOTS];
    __shared__ float sdsum[NWARP][NH];                       // per-row denominators

    const int warp = threadIdx.x >> 5;
    const int lane = threadIdx.x & 31;
    const int half = lane >> 4;                 // head-pair owner: heads {2*half, 2*half+1}
    const int p16  = lane & 15;                 // owns i in [p16*8, p16*8+8) of BOTH segments
    const int b3   = (p16 >> 3) & 1;            // head selector within the pair
    const int b2   = (p16 >> 2) & 1;            // segment selector (A/B)
    const int row  = blockIdx.x * NWARP + warp; // grid sized exactly: always < N_ROWS
    const float* xrow = x + (size_t)row * (SPLIT * IDIM);
    float4 (*slotp)[64] = ring[warp];
    const uint32_t mb0 = smem_u32(&mbar_s[warp][0]);    // barrier s at mb0 + 8*s
    const uint32_t ring0 = smem_u32(&ring[warp][0][0]); // slot s at ring0 + 1024*s

    // init this warp's mbarriers; make them visible to the async proxy
    if (lane == 0) {
#pragma unroll
        for (int s = 0; s < SLOTS; s++) mbar_init(mb0 + 8 * s);
        asm volatile("fence.proxy.async.shared::cta;" ::: "memory");
    }
    __syncwarp();

    // wq fragment: this lane's 8 i-values for its 2 heads (16 regs)
    float4 wqa0, wqa1, wqb0, wqb1;
    {
        const float4* ga = (const float4*)(g_wq + (2 * half) * IDIM + p16 * 8);
        const float4* gb = (const float4*)(g_wq + (2 * half + 1) * IDIM + p16 * 8);
        wqa0 = ga[0]; wqa1 = ga[1];
        wqb0 = gb[0]; wqb1 = gb[1];
    }

    // accumulators: 2 heads x 8 i (16 regs) + 2 denominators
    float4 xh0a, xh0b, xh1a, xh1b;
    xh0a = xh0b = xh1a = xh1b = make_float4(0.f, 0.f, 0.f, 0.f);
    float ds0 = 0.f, ds1 = 0.f;

    // prologue: launch PRE bulk copies (1KB each, lane 0 only)
    if (lane == 0) {
#pragma unroll
        for (int t = 0; t < PRE; t++) {
            mbar_expect_tx_1k(mb0 + 8 * t);
            bulk_1kb(ring0 + 1024 * t, xrow + t * 256, mb0 + 8 * t);
        }
    }

    for (int t = 0; t < MITERS; t++) {
        const int slot = t & (SLOTS - 1);
        mbar_wait(mb0 + 8 * slot, (t >> 2) & 1);   // acquire: TMA writes visible
        __syncwarp();

        // segment A = float4[0..32), segment B = float4[32..64); lane's i-slice of each
        float4 xa0 = slotp[slot][p16 * 2];
        float4 xa1 = slotp[slot][p16 * 2 + 1];
        float4 xb0v = slotp[slot][32 + p16 * 2];
        float4 xb1v = slotp[slot][32 + p16 * 2 + 1];

        // reissue into slot (t+PRE)&3 == t-1 (mod 4): all lanes' reads of it were
        // issued before this point (they passed this iteration's mbar_wait+syncwarp)
        const int nt = t + PRE;
        if (lane == 0 && nt < MITERS) {
            const int ns = nt & (SLOTS - 1);
            mbar_expect_tx_1k(mb0 + 8 * ns);
            bulk_1kb(ring0 + 1024 * ns, xrow + nt * 256, mb0 + 8 * ns);
        }

        // partial scores: 2 heads x 2 segments over this lane's 8 i's
        float pA0, pA1, pB0, pB1;
        {
            float a;
            a = xa0.x * wqa0.x;  a = fmaf(xa0.y, wqa0.y, a); a = fmaf(xa0.z, wqa0.z, a); a = fmaf(xa0.w, wqa0.w, a);
            a = fmaf(xa1.x, wqa1.x, a); a = fmaf(xa1.y, wqa1.y, a); a = fmaf(xa1.z, wqa1.z, a); a = fmaf(xa1.w, wqa1.w, a);
            pA0 = a;
            a = xa0.x * wqb0.x;  a = fmaf(xa0.y, wqb0.y, a); a = fmaf(xa0.z, wqb0.z, a); a = fmaf(xa0.w, wqb0.w, a);
            a = fmaf(xa1.x, wqb1.x, a); a = fmaf(xa1.y, wqb1.y, a); a = fmaf(xa1.z, wqb1.z, a); a = fmaf(xa1.w, wqb1.w, a);
            pA1 = a;
            a = xb0v.x * wqa0.x; a = fmaf(xb0v.y, wqa0.y, a); a = fmaf(xb0v.z, wqa0.z, a); a = fmaf(xb0v.w, wqa0.w, a);
            a = fmaf(xb1v.x, wqa1.x, a); a = fmaf(xb1v.y, wqa1.y, a); a = fmaf(xb1v.z, wqa1.z, a); a = fmaf(xb1v.w, wqa1.w, a);
            pB0 = a;
            a = xb0v.x * wqb0.x; a = fmaf(xb0v.y, wqb0.y, a); a = fmaf(xb0v.z, wqb0.z, a); a = fmaf(xb0v.w, wqb0.w, a);
            a = fmaf(xb1v.x, wqb1.x, a); a = fmaf(xb1v.y, wqb1.y, a); a = fmaf(xb1v.z, wqb1.z, a); a = fmaf(xb1v.w, wqb1.w, a);
            pB1 = a;
        }

        // specialized butterfly within the 16-lane half (5 shfls)
        float s1 = b3 ? pA0 : pA1;
        float r1 = __shfl_xor_sync(0xffffffffu, s1, 8);
        float uA = (b3 ? pA1 : pA0) + r1;
        float s2 = b3 ? pB0 : pB1;
        float r2 = __shfl_xor_sync(0xffffffffu, s2, 8);
        float uB = (b3 ? pB1 : pB0) + r2;
        float s3 = b2 ? uA : uB;
        float r3 = __shfl_xor_sync(0xffffffffu, s3, 4);
        float v  = (b2 ? uB : uA) + r3;              // (head 2*half+b3, seg b2)
        v += __shfl_xor_sync(0xffffffffu, v, 2);
        v += __shfl_xor_sync(0xffffffffu, v, 1);

        // leaky_relu -> exp, ONE per lane (|score| <~ 15 << 88, fp32-safe)
        float e = __expf(fmaxf(v, 0.2f * v));

        // allgather within the half (3 shfls): lane needs its 2 heads x 2 segs
        float g1 = __shfl_xor_sync(0xffffffffu, e, 4);
        float eX = b2 ? g1 : e;     // (head 2*half+b3, seg A)
        float eY = b2 ? e  : g1;    // (head 2*half+b3, seg B)
        float g2 = __shfl_xor_sync(0xffffffffu, eX, 8);
        float g3 = __shfl_xor_sync(0xffffffffu, eY, 8);
        float eA0 = b3 ? g2 : eX;   // (head 2*half,   seg A)
        float eA1 = b3 ? eX : g2;   // (head 2*half+1, seg A)
        float eB0 = b3 ? g3 : eY;   // (head 2*half,   seg B)
        float eB1 = b3 ? eY : g3;   // (head 2*half+1, seg B)

        // accumulate: 2 heads x 8 i x 2 segments
        ds0 += eA0 + eB0;
        ds1 += eA1 + eB1;
        xh0a.x = fmaf(eA0, xa0.x, xh0a.x); xh0a.y = fmaf(eA0, xa0.y, xh0a.y);
        xh0a.z = fmaf(eA0, xa0.z, xh0a.z); xh0a.w = fmaf(eA0, xa0.w, xh0a.w);
        xh0b.x = fmaf(eA0, xa1.x, xh0b.x); xh0b.y = fmaf(eA0, xa1.y, xh0b.y);
        xh0b.z = fmaf(eA0, xa1.z, xh0b.z); xh0b.w = fmaf(eA0, xa1.w, xh0b.w);
        xh1a.x = fmaf(eA1, xa0.x, xh1a.x); xh1a.y = fmaf(eA1, xa0.y, xh1a.y);
        xh1a.z = fmaf(eA1, xa0.z, xh1a.z); xh1a.w = fmaf(eA1, xa0.w, xh1a.w);
        xh1b.x = fmaf(eA1, xa1.x, xh1b.x); xh1b.y = fmaf(eA1, xa1.y, xh1b.y);
        xh1b.z = fmaf(eA1, xa1.z, xh1b.z); xh1b.w = fmaf(eA1, xa1.w, xh1b.w);

        xh0a.x = fmaf(eB0, xb0v.x, xh0a.x); xh0a.y = fmaf(eB0, xb0v.y, xh0a.y);
        xh0a.z = fmaf(eB0, xb0v.z, xh0a.z); xh0a.w = fmaf(eB0, xb0v.w, xh0a.w);
        xh0b.x = fmaf(eB0, xb1v.x, xh0b.x); xh0b.y = fmaf(eB0, xb1v.y, xh0b.y);
        xh0b.z = fmaf(eB0, xb1v.z, xh0b.z); xh0b.w = fmaf(eB0, xb1v.w, xh0b.w);
        xh1a.x = fmaf(eB1, xb0v.x, xh1a.x); xh1a.y = fmaf(eB1, xb0v.y, xh1a.y);
        xh1a.z = fmaf(eB1, xb0v.z, xh1a.z); xh1a.w = fmaf(eB1, xb0v.w, xh1a.w);
        xh1b.x = fmaf(eB1, xb1v.x, xh1b.x); xh1b.y = fmaf(eB1, xb1v.y, xh1b.y);
        xh1b.z = fmaf(eB1, xb1v.z, xh1b.z); xh1b.w = fmaf(eB1, xb1v.w, xh1b.w);
    }

    // ---- stage UNNORMALIZED accumulators for ALL rows into ring space ----
    // sx[warp*512] spans ring[warp>>1] regions — CROSS-WARP aliasing! A full
    // block barrier is REQUIRED first: it guarantees every warp has finished
    // its mainloop (all waits passed => no TMA in flight, no pending reads).
    // R13's omission of this barrier was the NaN bug.
    float* sx = (float*)&ring[0][0][0];   // row r at sx[r*512 + h*128 + i]
    __syncthreads();
    {
        float4* d0 = (float4*)(sx + warp * 512 + (2 * half) * IDIM + p16 * 8);
        d0[0] = xh0a;
        d0[1] = xh0b;
        float4* d1 = (float4*)(sx + warp * 512 + (2 * half + 1) * IDIM + p16 * 8);
        d1[0] = xh1a;
        d1[1] = xh1b;
    }
    if (p16 == 0) {
        sdsum[warp][2 * half]     = ds0;
        sdsum[warp][2 * half + 1] = ds1;
    }
    __syncthreads();

    // ---- cooperative epilogue: warp w = head w, lane owns 2 output cols,
    //      each W float2 load amortized across all 4 rows (8 FMAs/load) ----
    {
        const int hh = warp;              // head handled by this warp
        const int c0 = lane * 2;          // output columns c0, c0+1
        const float* Wp = W + ((size_t)hh * IDIM) * PD + c0;  // W[hh][i][c0], stride PD per i
        const float* sxh = sx + hh * IDIM;                    // + r*512 per row

        float2 acc[NWARP];
#pragma unroll
        for (int r = 0; r < NWARP; r++) acc[r] = make_float2(0.f, 0.f);

#pragma unroll 4
        for (int i = 0; i < IDIM; i++) {
            float2 wv = *(const float2*)(Wp + i * PD);         // shared by all 4 rows
#pragma unroll
            for (int r = 0; r < NWARP; r++) {
                float xv = sxh[r * 512 + i];                   // LDS broadcast
                acc[r].x = fmaf(xv, wv.x, acc[r].x);
                acc[r].y = fmaf(xv, wv.y, acc[r].y);
            }
        }

#pragma unroll
        for (int r = 0; r < NWARP; r++) {
            float inv = 1.0f / sdsum[r][hh];
            int row_r = blockIdx.x * NWARP + r;
            float2* op = (float2*)(out + (size_t)row_r * OUTD + hh * PD + c0);
            *op = make_float2(acc[r].x * inv, acc[r].y * inv);
        }
    }
}

extern "C" void kernel_launch(void* const* d_in, const int* in_sizes, int n_in,
                              void* d_out, int out_size) {
    // inputs: x [N, 12800], W [4,128,64], q [4,64] — identify defensively by size
    const float* x = (const float*)d_in[0];
    const float* W = (const float*)d_in[1];
    const float* q = (const float*)d_in[2];
    for (int i = 0; i < n_in && i < 3; i++) {
        if (in_sizes[i] == N_ROWS * SPLIT * IDIM) x = (const float*)d_in[i];
        else if (in_sizes[i] == NH * IDIM * PD)   W = (const float*)d_in[i];
        else if (in_sizes[i] == NH * PD)          q = (const float*)d_in[i];
    }
    float* out = (float*)d_out;

    wq_kernel<<<1, 512>>>(W, q);
    attn_kernel<<<N_ROWS / NWARP, NWARP * 32>>>(x, W, out);
}

// round 15
// speedup vs baseline: 1.1720x; 1.0485x over previous
#include <cuda_runtime.h>
#include <cuda_bf16.h>
#include <cstdint>

// Problem constants
#define N_ROWS 16384
#define SPLIT  100
#define IDIM   128
#define NH     4
#define PD     64
#define OUTD   (NH * PD)        // 256
#define MITERS (SPLIT / 2)      // 50 iters, 1KB (2 segments) each
#define SLOTS  4                // ring slots of 1KB each (4KB/warp)
#define PRE    3                // groups in flight (3KB/warp outstanding)
#define NWARP  4                // warps (rows) per block

// wq[h][i] = sum_o W[h,i,o] * q[h,o]  — precomputed by a tiny kernel
__device__ float g_wq[NH * IDIM];

__global__ void wq_kernel(const float* __restrict__ W, const float* __restrict__ q) {
    int idx = threadIdx.x;                     // 512 threads
    if (idx >= NH * IDIM) return;
    int h = idx >> 7, i = idx & 127;
    const float* Wr = W + ((size_t)(h * IDIM + i)) * PD;
    const float* qr = q + h * PD;
    float acc = 0.f;
#pragma unroll
    for (int o = 0; o < PD; o++) acc = fmaf(Wr[o], qr[o], acc);
    g_wq[idx] = acc;
}

__device__ __forceinline__ void cp16(void* smem_dst, const void* gsrc) {
    unsigned saddr = (unsigned)__cvta_generic_to_shared(smem_dst);
    asm volatile("cp.async.cg.shared.global [%0], [%1], 16;\n" :: "r"(saddr), "l"(gsrc));
}
__device__ __forceinline__ void cp_commit() { asm volatile("cp.async.commit_group;\n"); }
__device__ __forceinline__ void cp_wait_pre() { asm volatile("cp.async.wait_group %0;\n" :: "n"(PRE - 1)); }

// ---- packed fp32x2 helpers (Blackwell FFMA2 — only reachable via PTX) ----
#define FMA2(d, a, b, c) \
    asm("fma.rn.f32x2 %0, %1, %2, %3;" : "=l"(d) : "l"(a), "l"(b), "l"(c))
__device__ __forceinline__ unsigned long long pack2(float v) {
    unsigned long long r;
    asm("mov.b64 %0, {%1, %1};" : "=l"(r) : "f"(v));
    return r;
}
__device__ __forceinline__ float hadd2(unsigned long long v) {
    float lo, hi;
    asm("mov.b64 {%0, %1}, %2;" : "=f"(lo), "=f"(hi) : "l"(v));
    return lo + hi;
}

__global__ void __launch_bounds__(NWARP * 32, 8)
attn_kernel(const float* __restrict__ x, const float* __restrict__ W,
            float* __restrict__ out) {
    // per-warp ring: SLOTS slots of 2 segments (256 floats = 64 float4 = 1KB)
    __shared__ float4 ring[NWARP][SLOTS][64];    // 16 KB
    __shared__ float sdsum[NWARP][NH];           // per-row softmax denominators

    const int warp = threadIdx.x >> 5;
    const int lane = threadIdx.x & 31;
    const int half = lane >> 4;                 // head-pair owner: heads {2*half, 2*half+1}
    const int p16  = lane & 15;                 // owns i in [p16*8, p16*8+8) of BOTH segments
    const int b3   = (p16 >> 3) & 1;            // head selector within the pair
    const int b2   = (p16 >> 2) & 1;            // segment selector (A/B)
    const int row  = blockIdx.x * NWARP + warp; // grid sized exactly: always < N_ROWS
    const float* xrow = x + (size_t)row * (SPLIT * IDIM);
    float4 (*slotp)[64] = ring[warp];

    // wq fragment: this lane's 8 i-values for its 2 heads, as 4 f32x2 pairs each
    ulonglong2 wA0, wA1, wB0, wB1;   // head 2*half: wA0{p0,p1} wA1{p2,p3}; head 2*half+1: wB*
    {
        const ulonglong2* ga = (const ulonglong2*)(g_wq + (2 * half) * IDIM + p16 * 8);
        const ulonglong2* gb = (const ulonglong2*)(g_wq + (2 * half + 1) * IDIM + p16 * 8);
        wA0 = ga[0]; wA1 = ga[1];
        wB0 = gb[0]; wB1 = gb[1];
    }

    // accumulators: 2 heads x 8 i as f32x2 pairs (16 regs) + 2 denominators
    ulonglong2 h0lo, h0hi, h1lo, h1hi;   // head0: i-pairs 0-3 / 4-7 ; head1 same
    h0lo = h0hi = h1lo = h1hi = make_ulonglong2(0ull, 0ull);
    float ds0 = 0.f, ds1 = 0.f;

    // prologue: fill PRE pipeline stages (lane copies float4[lane*2], [lane*2+1])
#pragma unroll
    for (int t = 0; t < PRE; t++) {
        const float* src = xrow + t * 256 + lane * 8;
        cp16(&slotp[t][lane * 2],     src);
        cp16(&slotp[t][lane * 2 + 1], src + 4);
        cp_commit();
    }

    for (int t = 0; t < MITERS; t++) {
        cp_wait_pre();
        __syncwarp();    // lanes read bytes cp'd by OTHER lanes (both halves read both segs)

        const int slot = t & (SLOTS - 1);
        // segment A = float4[0..32), segment B = float4[32..64); lane's i-slice of each,
        // loaded as f32x2 pairs (same LDS.128s, different register typing)
        ulonglong2 xA0 = *(const ulonglong2*)&slotp[slot][p16 * 2];
        ulonglong2 xA1 = *(const ulonglong2*)&slotp[slot][p16 * 2 + 1];
        ulonglong2 xB0 = *(const ulonglong2*)&slotp[slot][32 + p16 * 2];
        ulonglong2 xB1 = *(const ulonglong2*)&slotp[slot][32 + p16 * 2 + 1];

        // issue next stage; commit UNCONDITIONALLY (wait_group is commit-order keyed)
        const int nt = t + PRE;
        if (nt < MITERS) {
            const int ns = nt & (SLOTS - 1);
            const float* src = xrow + nt * 256 + lane * 8;
            cp16(&slotp[ns][lane * 2],     src);
            cp16(&slotp[ns][lane * 2 + 1], src + 4);
        }
        cp_commit();

        // partial scores: 2 heads x 2 segments over this lane's 8 i's (FFMA2 chains)
        float pA0, pA1, pB0, pB1;
        {
            unsigned long long a;
            a = 0ull;
            FMA2(a, xA0.x, wA0.x, a); FMA2(a, xA0.y, wA0.y, a);
            FMA2(a, xA1.x, wA1.x, a); FMA2(a, xA1.y, wA1.y, a);
            pA0 = hadd2(a);
            a = 0ull;
            FMA2(a, xA0.x, wB0.x, a); FMA2(a, xA0.y, wB0.y, a);
            FMA2(a, xA1.x, wB1.x, a); FMA2(a, xA1.y, wB1.y, a);
            pA1 = hadd2(a);
            a = 0ull;
            FMA2(a, xB0.x, wA0.x, a); FMA2(a, xB0.y, wA0.y, a);
            FMA2(a, xB1.x, wA1.x, a); FMA2(a, xB1.y, wA1.y, a);
            pB0 = hadd2(a);
            a = 0ull;
            FMA2(a, xB0.x, wB0.x, a); FMA2(a, xB0.y, wB0.y, a);
            FMA2(a, xB1.x, wB1.x, a); FMA2(a, xB1.y, wB1.y, a);
            pB1 = hadd2(a);
        }

        // specialized butterfly within the 16-lane half (5 shfls)
        float s1 = b3 ? pA0 : pA1;
        float r1 = __shfl_xor_sync(0xffffffffu, s1, 8);
        float uA = (b3 ? pA1 : pA0) + r1;
        float s2 = b3 ? pB0 : pB1;
        float r2 = __shfl_xor_sync(0xffffffffu, s2, 8);
        float uB = (b3 ? pB1 : pB0) + r2;
        float s3 = b2 ? uA : uB;
        float r3 = __shfl_xor_sync(0xffffffffu, s3, 4);
        float v  = (b2 ? uB : uA) + r3;              // (head 2*half+b3, seg b2)
        v += __shfl_xor_sync(0xffffffffu, v, 2);
        v += __shfl_xor_sync(0xffffffffu, v, 1);

        // leaky_relu -> exp, ONE per lane (|score| <~ 15 << 88, fp32-safe)
        float e = __expf(fmaxf(v, 0.2f * v));

        // allgather within the half (3 shfls): lane needs its 2 heads x 2 segs
        float g1 = __shfl_xor_sync(0xffffffffu, e, 4);
        float eX = b2 ? g1 : e;     // (head 2*half+b3, seg A)
        float eY = b2 ? e  : g1;    // (head 2*half+b3, seg B)
        float g2 = __shfl_xor_sync(0xffffffffu, eX, 8);
        float g3 = __shfl_xor_sync(0xffffffffu, eY, 8);
        float eA0 = b3 ? g2 : eX;   // (head 2*half,   seg A)
        float eA1 = b3 ? eX : g2;   // (head 2*half+1, seg A)
        float eB0 = b3 ? g3 : eY;   // (head 2*half,   seg B)
        float eB1 = b3 ? eY : g3;   // (head 2*half+1, seg B)

        // accumulate with FFMA2: 2 heads x 4 pairs x 2 segments = 16 FFMA2
        ds0 += eA0 + eB0;
        ds1 += eA1 + eB1;
        {
            unsigned long long pA0e = pack2(eA0), pA1e = pack2(eA1);
            unsigned long long pB0e = pack2(eB0), pB1e = pack2(eB1);
            FMA2(h0lo.x, pA0e, xA0.x, h0lo.x); FMA2(h0lo.y, pA0e, xA0.y, h0lo.y);
            FMA2(h0hi.x, pA0e, xA1.x, h0hi.x); FMA2(h0hi.y, pA0e, xA1.y, h0hi.y);
            FMA2(h1lo.x, pA1e, xA0.x, h1lo.x); FMA2(h1lo.y, pA1e, xA0.y, h1lo.y);
            FMA2(h1hi.x, pA1e, xA1.x, h1hi.x); FMA2(h1hi.y, pA1e, xA1.y, h1hi.y);
            FMA2(h0lo.x, pB0e, xB0.x, h0lo.x); FMA2(h0lo.y, pB0e, xB0.y, h0lo.y);
            FMA2(h0hi.x, pB0e, xB1.x, h0hi.x); FMA2(h0hi.y, pB0e, xB1.y, h0hi.y);
            FMA2(h1lo.x, pB1e, xB0.x, h1lo.x); FMA2(h1lo.y, pB1e, xB0.y, h1lo.y);
            FMA2(h1hi.x, pB1e, xB1.x, h1hi.x); FMA2(h1hi.y, pB1e, xB1.y, h1hi.y);
        }
    }

    // ---- stage UNNORMALIZED accumulators for ALL rows into ring space ----
    // Row r's region aliases other warps' ring slots: full block barrier first.
    // Halves own disjoint heads, lanes own disjoint i — no combine needed.
    float* sx = (float*)&ring[0][0][0];   // row r at sx[r*512 + h*128 + i]
    __syncthreads();
    {
        ulonglong2* d0 = (ulonglong2*)(sx + warp * 512 + (2 * half) * IDIM + p16 * 8);
        d0[0] = h0lo;
        d0[1] = h0hi;
        ulonglong2* d1 = (ulonglong2*)(sx + warp * 512 + (2 * half + 1) * IDIM + p16 * 8);
        d1[0] = h1lo;
        d1[1] = h1hi;
    }
    if (p16 == 0) {
        sdsum[warp][2 * half]     = ds0;
        sdsum[warp][2 * half + 1] = ds1;
    }
    __syncthreads();

    // ---- cooperative epilogue: warp w = head w, lane owns 2 output cols,
    //      each W float2 load amortized across all 4 rows (8 FMAs/load) ----
    {
        const int hh = warp;              // head handled by this warp
        const int c0 = lane * 2;          // output columns c0, c0+1
        const float* Wp = W + ((size_t)hh * IDIM) * PD + c0;  // W[hh][i][c0], stride PD per i
        const float* sxh = sx + hh * IDIM;                    // + r*512 per row

        float2 acc[NWARP];
#pragma unroll
        for (int r = 0; r < NWARP; r++) acc[r] = make_float2(0.f, 0.f);

#pragma unroll 4
        for (int i = 0; i < IDIM; i++) {
            float2 wv = *(const float2*)(Wp + i * PD);         // shared by all 4 rows
#pragma unroll
            for (int r = 0; r < NWARP; r++) {
                float xv = sxh[r * 512 + i];                   // LDS broadcast
                acc[r].x = fmaf(xv, wv.x, acc[r].x);
                acc[r].y = fmaf(xv, wv.y, acc[r].y);
            }
        }

#pragma unroll
        for (int r = 0; r < NWARP; r++) {
            float inv = 1.0f / sdsum[r][hh];
            int row_r = blockIdx.x * NWARP + r;
            float2* op = (float2*)(out + (size_t)row_r * OUTD + hh * PD + c0);
            *op = make_float2(acc[r].x * inv, acc[r].y * inv);
        }
    }
}

extern "C" void kernel_launch(void* const* d_in, const int* in_sizes, int n_in,
                              void* d_out, int out_size) {
    // inputs: x [N, 12800], W [4,128,64], q [4,64] — identify defensively by size
    const float* x = (const float*)d_in[0];
    const float* W = (const float*)d_in[1];
    const float* q = (const float*)d_in[2];
    for (int i = 0; i < n_in && i < 3; i++) {
        if (in_sizes[i] == N_ROWS * SPLIT * IDIM) x = (const float*)d_in[i];
        else if (in_sizes[i] == NH * IDIM * PD)   W = (const float*)d_in[i];
        else if (in_sizes[i] == NH * PD)          q = (const float*)d_in[i];
    }
    float* out = (float*)d_out;

    wq_kernel<<<1, 512>>>(W, q);
    attn_kernel<<<N_ROWS / NWARP, NWARP * 32>>>(x, W, out);
}